// round 12
// baseline (speedup 1.0000x reference)
#include <cuda_runtime.h>
#include <cuda_fp16.h>
#include <cstdint>

#define BATCH   8192
#define DIM     64
#define HID     128
#define NSTEPS  100
#define THREADS 512
#define NBLK    128

// ---- smem layout (bytes) ----
#define P1 144u   // W1^T row pitch: 64 fp16 = 128B + 16B pad
#define P2 272u   // W2^T row pitch: 128 fp16 = 256B + 16B pad
#define W1D_OFF 0u
#define W1G_OFF 18432u       // 128*144
#define W2D_OFF 36864u
#define W2G_OFF 54272u       // + 64*272
#define B1D_OFF 71680u
#define B1G_OFF 72192u
#define B2D_OFF 72704u
#define B2G_OFF 72960u
#define EX_OFF  73216u       // per tile 16KB: Hd, Hg, fC2, gC2 (4KB each)
#define SMEM_TOTAL (73216u + 4u * 16384u)   // 138752

__device__ __forceinline__ uint32_t smem_u32(const void* p) {
    uint32_t a;
    asm("{ .reg .u64 t; cvta.to.shared.u64 t, %1; cvt.u32.u64 %0, t; }"
        : "=r"(a) : "l"(p));
    return a;
}

__device__ __forceinline__ uint32_t tanh2(uint32_t v) {
    uint32_t r;
    asm("tanh.approx.f16x2 %0, %1;" : "=r"(r) : "r"(v));
    return r;
}

__device__ __forceinline__ void mma_f16(float* c, const uint32_t* a,
                                        uint32_t b0, uint32_t b1) {
    asm volatile(
        "mma.sync.aligned.m16n8k16.row.col.f32.f16.f16.f32 "
        "{%0,%1,%2,%3}, {%4,%5,%6,%7}, {%8,%9}, {%0,%1,%2,%3};"
        : "+f"(c[0]), "+f"(c[1]), "+f"(c[2]), "+f"(c[3])
        : "r"(a[0]), "r"(a[1]), "r"(a[2]), "r"(a[3]), "r"(b0), "r"(b1));
}

__device__ __forceinline__ void ldsm4(uint32_t* r, uint32_t addr) {
    asm volatile("ldmatrix.sync.aligned.m8n8.x4.shared.b16 {%0,%1,%2,%3}, [%4];"
                 : "=r"(r[0]), "=r"(r[1]), "=r"(r[2]), "=r"(r[3]) : "r"(addr));
}

__device__ __forceinline__ uint32_t packh(float lo, float hi) {
    __half2 h = __floats2half2_rn(lo, hi);
    return *reinterpret_cast<uint32_t*>(&h);
}

#define BARRIER(id) asm volatile("bar.sync %0, %1;" :: "r"(id), "n"(128) : "memory")

__global__ void __launch_bounds__(THREADS, 1)
sde_role_kernel(const float* __restrict__ x0,
                const float* __restrict__ noise,
                const float* __restrict__ Wd1, const float* __restrict__ bd1,
                const float* __restrict__ Wd2, const float* __restrict__ bd2,
                const float* __restrict__ Wg1, const float* __restrict__ bg1,
                const float* __restrict__ Wg2, const float* __restrict__ bg2,
                float* __restrict__ out)
{
    extern __shared__ char smc[];
    const uint32_t smem_base = smem_u32(smc);
    const int tid = threadIdx.x;

    // ---- stage weights to smem (fp16, transposed [n][k], padded pitch) ----
    for (int idx = tid; idx < DIM * HID; idx += THREADS) {     // W1: [64 k][128 n]
        int k = idx >> 7, n = idx & 127;
        *(__half*)(smc + W1D_OFF + (uint32_t)n * P1 + 2*k) = __float2half_rn(Wd1[idx]);
        *(__half*)(smc + W1G_OFF + (uint32_t)n * P1 + 2*k) = __float2half_rn(Wg1[idx]);
    }
    for (int idx = tid; idx < HID * DIM; idx += THREADS) {     // W2: [128 k][64 n]
        int k = idx >> 6, n = idx & 63;
        *(__half*)(smc + W2D_OFF + (uint32_t)n * P2 + 2*k) = __float2half_rn(Wd2[idx]);
        *(__half*)(smc + W2G_OFF + (uint32_t)n * P2 + 2*k) = __float2half_rn(Wg2[idx]);
    }
    for (int i = tid; i < HID; i += THREADS) {
        ((float*)(smc + B1D_OFF))[i] = bd1[i];
        ((float*)(smc + B1G_OFF))[i] = bg1[i];
    }
    for (int i = tid; i < DIM; i += THREADS) {
        ((float*)(smc + B2D_OFF))[i] = bd2[i];
        ((float*)(smc + B2G_OFF))[i] = bg2[i];
    }
    __syncthreads();

    const int wid  = tid >> 5, lane = tid & 31;
    const int tile = wid & 3;           // SMSP == tile: all 4 roles co-resident
    const int role = wid >> 2;          // 0=G1d 1=G1g 2=G2d 3=G2g
    const int g = lane >> 2;
    const int cpair = (lane & 3) * 2;
    const int rowT = blockIdx.x * 64 + tile * 16 + g;   // rows rowT, rowT+8
    const int barid = 1 + tile;

    // ldmatrix per-lane address components (proven layout)
    const int rowA = (lane & 7) + ((lane >> 4) << 3);
    const uint32_t colo = (uint32_t)((lane >> 3) & 1) * 16u;

    // exchange regions for this tile
    char* EXT = smc + EX_OFF + (uint32_t)tile * 16384u;
    char* Hd  = EXT;             // G1d -> G2d
    char* Hg  = EXT + 4096;      // G1g -> G2g
    char* Cf  = EXT + 8192;      // G2d -> G1*
    char* Cg  = EXT + 12288;     // G2g -> G1*

    const float DTC = 0.01f;
    const float SDT = 0.1f;

    if (role < 2) {
        // ================= layer-1 + update warps =================
        const bool isD = (role == 0);
        const uint32_t wbase = smem_base + (isD ? W1D_OFF : W1G_OFF)
                             + (uint32_t)rowA * P1 + colo;
        const float* sb1  = (const float*)(smc + (isD ? B1D_OFF : B1G_OFF));
        const float* sb2d = (const float*)(smc + B2D_OFF);
        const float* sb2g = (const float*)(smc + B2G_OFF);
        char* Hwr = isD ? Hd : Hg;
        char* lp16 = (char*)0 + (uint32_t)lane * 16u;   // lane byte offset helper
        (void)lp16;

        // cache W1 fragments: 8 n16-tiles x 4 k16-chunks x 4 regs = 128 regs
        uint32_t B1f[8][4][4];
        #pragma unroll
        for (int t2 = 0; t2 < 8; t2++)
            #pragma unroll
            for (int kk = 0; kk < 4; kk++)
                ldsm4(B1f[t2][kk], wbase + (uint32_t)t2 * (16u * P1) + (uint32_t)kk * 32u);

        // x state + A-fragments
        float x[8][4];
        uint32_t xh[4][4];
        #pragma unroll
        for (int t = 0; t < 8; t++) {
            float2 v0 = *(const float2*)(x0 + (size_t)rowT * DIM + 8*t + cpair);
            float2 v1 = *(const float2*)(x0 + (size_t)(rowT + 8) * DIM + 8*t + cpair);
            x[t][0] = v0.x; x[t][1] = v0.y; x[t][2] = v1.x; x[t][3] = v1.y;
            if (isD) {
                *(float2*)(out + (size_t)rowT * DIM + 8*t + cpair) = v0;
                *(float2*)(out + (size_t)(rowT + 8) * DIM + 8*t + cpair) = v1;
            }
            int kk = t >> 1, s = (t & 1) * 2;
            xh[kk][s]     = packh(v0.x, v0.y);
            xh[kk][s + 1] = packh(v1.x, v1.y);
        }

        #pragma unroll 1
        for (int step = 0; step < NSTEPS; ++step) {
            // ---- phase A: GEMM1 + bias + tanh(f16x2), stream H to smem ----
            #pragma unroll
            for (int t2 = 0; t2 < 8; t2++) {
                float cLo[4] = {0,0,0,0}, cHi[4] = {0,0,0,0};
                #pragma unroll
                for (int kk = 0; kk < 4; kk++) {
                    mma_f16(cLo, xh[kk], B1f[t2][kk][0], B1f[t2][kk][1]);
                    mma_f16(cHi, xh[kk], B1f[t2][kk][2], B1f[t2][kk][3]);
                }
                float2 blo = *(const float2*)(sb1 + 16*t2 + cpair);
                float2 bhi = *(const float2*)(sb1 + 16*t2 + 8 + cpair);
                uint32_t p0 = tanh2(packh(cLo[0] + blo.x, cLo[1] + blo.y));
                uint32_t p1 = tanh2(packh(cLo[2] + blo.x, cLo[3] + blo.y));
                uint32_t p2 = tanh2(packh(cHi[0] + bhi.x, cHi[1] + bhi.y));
                uint32_t p3 = tanh2(packh(cHi[2] + bhi.x, cHi[3] + bhi.y));
                // chunk t2 == G2's A-fragment for k16-chunk t2
                *(uint4*)(Hwr + t2 * 512 + lane * 16) = make_uint4(p0, p1, p2, p3);
            }
            BARRIER(barid);

            // ---- overlap with phase B: load + scale noise ----
            float nz[8][4];
            {
                const float* nb = noise + (size_t)step * BATCH * DIM;
                #pragma unroll
                for (int t = 0; t < 8; t++) {
                    float2 v0 = *(const float2*)(nb + (size_t)rowT * DIM + 8*t + cpair);
                    float2 v1 = *(const float2*)(nb + (size_t)(rowT + 8) * DIM + 8*t + cpair);
                    nz[t][0] = v0.x * SDT; nz[t][1] = v0.y * SDT;
                    nz[t][2] = v1.x * SDT; nz[t][3] = v1.y * SDT;
                }
            }
            BARRIER(barid);

            // ---- update (redundant on G1d and G1g; G1d stores traj) ----
            float* ob = out + (size_t)(step + 1) * BATCH * DIM;
            #pragma unroll
            for (int t = 0; t < 8; t++) {
                float4 fv = *(const float4*)(Cf + t * 512 + lane * 16);
                float4 gv = *(const float4*)(Cg + t * 512 + lane * 16);
                float2 b2d = *(const float2*)(sb2d + 8*t + cpair);
                float2 b2g = *(const float2*)(sb2g + 8*t + cpair);
                x[t][0] = fmaf(gv.x + b2g.x, nz[t][0], fmaf(fv.x + b2d.x, DTC, x[t][0]));
                x[t][1] = fmaf(gv.y + b2g.y, nz[t][1], fmaf(fv.y + b2d.y, DTC, x[t][1]));
                x[t][2] = fmaf(gv.z + b2g.x, nz[t][2], fmaf(fv.z + b2d.x, DTC, x[t][2]));
                x[t][3] = fmaf(gv.w + b2g.y, nz[t][3], fmaf(fv.w + b2d.y, DTC, x[t][3]));
                if (isD) {
                    *(float2*)(ob + (size_t)rowT * DIM + 8*t + cpair) =
                        make_float2(x[t][0], x[t][1]);
                    *(float2*)(ob + (size_t)(rowT + 8) * DIM + 8*t + cpair) =
                        make_float2(x[t][2], x[t][3]);
                }
                int kk = t >> 1, s = (t & 1) * 2;
                xh[kk][s]     = packh(x[t][0], x[t][1]);
                xh[kk][s + 1] = packh(x[t][2], x[t][3]);
            }
        }
    } else {
        // ================= layer-2 warps =================
        const bool isD = (role == 2);
        const uint32_t wbase = smem_base + (isD ? W2D_OFF : W2G_OFF)
                             + (uint32_t)rowA * P2 + colo;
        char* Hrd = isD ? Hd : Hg;
        char* Cwr = isD ? Cf : Cg;

        // cache W2 fragments: 4 n16-groups x 8 k16-chunks x 4 regs = 128 regs
        uint32_t B2f[4][8][4];
        #pragma unroll
        for (int g2i = 0; g2i < 4; g2i++)
            #pragma unroll
            for (int kk = 0; kk < 8; kk++)
                ldsm4(B2f[g2i][kk], wbase + (uint32_t)g2i * (16u * P2) + (uint32_t)kk * 32u);

        #pragma unroll 1
        for (int step = 0; step < NSTEPS; ++step) {
            BARRIER(barid);            // wait for H

            uint32_t Ha[8][4];
            #pragma unroll
            for (int kk = 0; kk < 8; kk++) {
                uint4 v = *(const uint4*)(Hrd + kk * 512 + lane * 16);
                Ha[kk][0] = v.x; Ha[kk][1] = v.y; Ha[kk][2] = v.z; Ha[kk][3] = v.w;
            }

            float C2[8][4];
            #pragma unroll
            for (int t = 0; t < 8; t++)
                { C2[t][0]=0.f; C2[t][1]=0.f; C2[t][2]=0.f; C2[t][3]=0.f; }
            #pragma unroll
            for (int kk = 0; kk < 8; kk++) {
                #pragma unroll
                for (int g2i = 0; g2i < 4; g2i++) {
                    mma_f16(C2[2*g2i],   Ha[kk], B2f[g2i][kk][0], B2f[g2i][kk][1]);
                    mma_f16(C2[2*g2i+1], Ha[kk], B2f[g2i][kk][2], B2f[g2i][kk][3]);
                }
            }

            #pragma unroll
            for (int t = 0; t < 8; t++)
                *(float4*)(Cwr + t * 512 + lane * 16) =
                    make_float4(C2[t][0], C2[t][1], C2[t][2], C2[t][3]);
            BARRIER(barid);            // C2 published; G1 updates next
        }
    }
}

extern "C" void kernel_launch(void* const* d_in, const int* in_sizes, int n_in,
                              void* d_out, int out_size)
{
    const float* x0    = (const float*)d_in[0];
    const float* noise = (const float*)d_in[2];
    const float* Wd1   = (const float*)d_in[3];
    const float* bd1   = (const float*)d_in[4];
    const float* Wd2   = (const float*)d_in[5];
    const float* bd2   = (const float*)d_in[6];
    const float* Wg1   = (const float*)d_in[7];
    const float* bg1   = (const float*)d_in[8];
    const float* Wg2   = (const float*)d_in[9];
    const float* bg2   = (const float*)d_in[10];
    float* out = (float*)d_out;

    cudaFuncSetAttribute(sde_role_kernel,
                         cudaFuncAttributeMaxDynamicSharedMemorySize, SMEM_TOTAL);
    sde_role_kernel<<<NBLK, THREADS, SMEM_TOTAL>>>(
        x0, noise, Wd1, bd1, Wd2, bd2, Wg1, bg1, Wg2, bg2, out);
}

// round 15
// speedup vs baseline: 1.6345x; 1.6345x over previous
#include <cuda_runtime.h>
#include <cuda_fp16.h>
#include <cstdint>

#define BATCH   8192
#define DIM     64
#define HID     128
#define NSTEPS  100
#define THREADS 256
#define NBLK    128

// ---- smem layout (bytes) ----
#define P1 144u   // W1^T row pitch: 64 fp16 = 128B + 16B pad
#define P2 272u   // W2^T row pitch: 128 fp16 = 256B + 16B pad
#define W1D_OFF 0u
#define W1G_OFF 18432u       // 128*144
#define W2D_OFF 36864u
#define W2G_OFF 54272u       // + 64*272
#define B1D_OFF 71680u
#define B1G_OFF 72192u
#define B2D_OFF 72704u
#define B2G_OFF 72960u
#define XFRAG_OFF 73216u     // [4 tiles][4 kk][32 lanes][16B] = 8KB
#define GEX_OFF   81408u     // [4 tiles][8 t][32 lanes][16B] = 16KB
#define SMEM_TOTAL 97792u

__device__ __forceinline__ uint32_t smem_u32(const void* p) {
    uint32_t a;
    asm("{ .reg .u64 t; cvta.to.shared.u64 t, %1; cvt.u32.u64 %0, t; }"
        : "=r"(a) : "l"(p));
    return a;
}

__device__ __forceinline__ float tanh_fast(float v) {
    float r;
    asm("tanh.approx.f32 %0, %1;" : "=f"(r) : "f"(v));
    return r;
}

__device__ __forceinline__ void mma_f16(float* c, const uint32_t* a,
                                        uint32_t b0, uint32_t b1) {
    asm volatile(
        "mma.sync.aligned.m16n8k16.row.col.f32.f16.f16.f32 "
        "{%0,%1,%2,%3}, {%4,%5,%6,%7}, {%8,%9}, {%0,%1,%2,%3};"
        : "+f"(c[0]), "+f"(c[1]), "+f"(c[2]), "+f"(c[3])
        : "r"(a[0]), "r"(a[1]), "r"(a[2]), "r"(a[3]), "r"(b0), "r"(b1));
}

__device__ __forceinline__ void ldsm4(uint32_t* r, uint32_t addr) {
    asm volatile("ldmatrix.sync.aligned.m8n8.x4.shared.b16 {%0,%1,%2,%3}, [%4];"
                 : "=r"(r[0]), "=r"(r[1]), "=r"(r[2]), "=r"(r[3]) : "r"(addr));
}

// pack (lo element, hi element) -> fp16x2  (lo in low 16 bits)
__device__ __forceinline__ uint32_t packh(float lo, float hi) {
    __half2 h = __floats2half2_rn(lo, hi);
    return *reinterpret_cast<uint32_t*>(&h);
}

__device__ __forceinline__ void pack_frags(const float (&x)[8][4],
    uint32_t (&xh)[4][4])
{
    #pragma unroll
    for (int kk = 0; kk < 4; kk++) {
        xh[kk][0] = packh(x[2*kk][0],   x[2*kk][1]);
        xh[kk][1] = packh(x[2*kk][2],   x[2*kk][3]);
        xh[kk][2] = packh(x[2*kk+1][0], x[2*kk+1][1]);
        xh[kk][3] = packh(x[2*kk+1][2], x[2*kk+1][3]);
    }
}

__global__ void __launch_bounds__(THREADS, 1)
sde_wreg_kernel(const float* __restrict__ x0,
                const float* __restrict__ noise,
                const float* __restrict__ Wd1, const float* __restrict__ bd1,
                const float* __restrict__ Wd2, const float* __restrict__ bd2,
                const float* __restrict__ Wg1, const float* __restrict__ bg1,
                const float* __restrict__ Wg2, const float* __restrict__ bg2,
                float* __restrict__ out)
{
    extern __shared__ char smc[];
    const uint32_t smem_base = smem_u32(smc);
    const int tid = threadIdx.x;

    // ---- stage weights (fp16, transposed [n][k], padded pitch) ----
    for (int idx = tid; idx < DIM * HID; idx += THREADS) {     // W1: [64 k][128 n]
        int k = idx >> 7, n = idx & 127;
        *(__half*)(smc + W1D_OFF + (uint32_t)n * P1 + 2*k) = __float2half_rn(Wd1[idx]);
        *(__half*)(smc + W1G_OFF + (uint32_t)n * P1 + 2*k) = __float2half_rn(Wg1[idx]);
    }
    for (int idx = tid; idx < HID * DIM; idx += THREADS) {     // W2: [128 k][64 n]
        int k = idx >> 6, n = idx & 63;
        *(__half*)(smc + W2D_OFF + (uint32_t)n * P2 + 2*k) = __float2half_rn(Wd2[idx]);
        *(__half*)(smc + W2G_OFF + (uint32_t)n * P2 + 2*k) = __float2half_rn(Wg2[idx]);
    }
    for (int i = tid; i < HID; i += THREADS) {
        ((float*)(smc + B1D_OFF))[i] = bd1[i];
        ((float*)(smc + B1G_OFF))[i] = bg1[i];
    }
    for (int i = tid; i < DIM; i += THREADS) {
        ((float*)(smc + B2D_OFF))[i] = bd2[i];
        ((float*)(smc + B2G_OFF))[i] = bg2[i];
    }
    __syncthreads();

    const int wid  = tid >> 5, lane = tid & 31;
    const int tile = wid & 3;              // warp pair (tile, tile+4) on SMSP 'tile'
    const bool isF = (wid < 4);            // drift/update warp vs diffusion/noise warp
    const int g = lane >> 2;
    const int cpair = (lane & 3) * 2;
    const int row0 = blockIdx.x * 64 + tile * 16 + g;
    const int barid = 1 + tile;

    // ldmatrix per-lane base address components
    const int rowA = (lane & 7) + ((lane >> 4) << 3);
    const uint32_t colo = (uint32_t)((lane >> 3) & 1) * 16u;
    const uint32_t g1 = smem_base + (isF ? W1D_OFF : W1G_OFF) + (uint32_t)rowA * P1 + colo;
    const uint32_t g2 = smem_base + (isF ? W2D_OFF : W2G_OFF) + (uint32_t)rowA * P2 + colo;

    const float* sb1  = (const float*)(smc + (isF ? B1D_OFF : B1G_OFF));
    const float* sb2d = (const float*)(smc + B2D_OFF);
    const float* sb2g = (const float*)(smc + B2G_OFF);

    // exchange buffers (lane-to-lane, conflict-free 16B/lane)
    char* xfp = smc + XFRAG_OFF + (uint32_t)tile * 2048u + (uint32_t)lane * 16u;
    char* gxp = smc + GEX_OFF   + (uint32_t)tile * 4096u + (uint32_t)lane * 16u;

    // ---- cache own W2 B-fragments in registers: 8 kk x 4 n16 x 4 = 128 regs ----
    uint32_t B2f[8][4][4];
    #pragma unroll
    for (int g2i = 0; g2i < 4; g2i++)
        #pragma unroll
        for (int kk = 0; kk < 8; kk++)
            ldsm4(B2f[kk][g2i], g2 + (uint32_t)g2i * (16u * P2) + (uint32_t)kk * 32u);

    // ---- init: both warps load x0, pack frags; f-warp keeps x + writes out[0]
    float x[8][4];
    uint32_t xh[4][4];
    #pragma unroll
    for (int t = 0; t < 8; t++) {
        float2 v0 = *(const float2*)(x0 + (size_t)row0 * DIM + 8*t + cpair);
        float2 v1 = *(const float2*)(x0 + (size_t)(row0 + 8) * DIM + 8*t + cpair);
        x[t][0] = v0.x; x[t][1] = v0.y; x[t][2] = v1.x; x[t][3] = v1.y;
        if (isF) {
            *(float2*)(out + (size_t)row0 * DIM + 8*t + cpair) = v0;
            *(float2*)(out + (size_t)(row0 + 8) * DIM + 8*t + cpair) = v1;
        }
    }
    pack_frags(x, xh);

    const float DTC = 0.01f;
    const float SDT = 0.1f;

    #pragma unroll 1
    for (int step = 0; step < NSTEPS; ++step) {
        float nz[8][4];
        if (!isF) {   // g-warp owns the noise: LDG overlaps its GEMMs
            const float* nb = noise + (size_t)step * BATCH * DIM;
            #pragma unroll
            for (int t = 0; t < 8; t++) {
                float2 v0 = *(const float2*)(nb + (size_t)row0 * DIM + 8*t + cpair);
                float2 v1 = *(const float2*)(nb + (size_t)(row0 + 8) * DIM + 8*t + cpair);
                nz[t][0] = v0.x * SDT; nz[t][1] = v0.y * SDT;
                nz[t][2] = v1.x * SDT; nz[t][3] = v1.y * SDT;
            }
        }

        // ---- GEMM1 fused with bias+tanh per n16-tile (low transient regs) ----
        uint32_t Hh[16][2];
        #pragma unroll
        for (int t2 = 0; t2 < 8; t2++) {
            float cLo[4] = {0,0,0,0}, cHi[4] = {0,0,0,0};
            #pragma unroll
            for (int kk = 0; kk < 4; kk++) {
                uint32_t b[4];
                ldsm4(b, g1 + (uint32_t)t2 * (16u * P1) + (uint32_t)kk * 32u);
                mma_f16(cLo, xh[kk], b[0], b[1]);
                mma_f16(cHi, xh[kk], b[2], b[3]);
            }
            float2 blo = *(const float2*)(sb1 + 16*t2 + cpair);
            float2 bhi = *(const float2*)(sb1 + 16*t2 + 8 + cpair);
            Hh[2*t2][0]   = packh(tanh_fast(cLo[0] + blo.x), tanh_fast(cLo[1] + blo.y));
            Hh[2*t2][1]   = packh(tanh_fast(cLo[2] + blo.x), tanh_fast(cLo[3] + blo.y));
            Hh[2*t2+1][0] = packh(tanh_fast(cHi[0] + bhi.x), tanh_fast(cHi[1] + bhi.y));
            Hh[2*t2+1][1] = packh(tanh_fast(cHi[2] + bhi.x), tanh_fast(cHi[3] + bhi.y));
        }

        // ---- GEMM2: all operands in registers (zero LDSM) ----
        float a2[8][4];
        #pragma unroll
        for (int t = 0; t < 8; t++) { a2[t][0]=0.f; a2[t][1]=0.f; a2[t][2]=0.f; a2[t][3]=0.f; }
        #pragma unroll
        for (int kk = 0; kk < 8; kk++) {
            uint32_t a[4] = {Hh[2*kk][0], Hh[2*kk][1], Hh[2*kk+1][0], Hh[2*kk+1][1]};
            #pragma unroll
            for (int g2i = 0; g2i < 4; g2i++) {
                mma_f16(a2[2*g2i],   a, B2f[kk][g2i][0], B2f[kk][g2i][1]);
                mma_f16(a2[2*g2i+1], a, B2f[kk][g2i][2], B2f[kk][g2i][3]);
            }
        }

        if (!isF) {
            // g-warp: publish (g + bias) * (dw*sqrt_dt), then fetch next-step x frags
            #pragma unroll
            for (int t = 0; t < 8; t++) {
                float b0 = sb2g[8*t + cpair], b1 = sb2g[8*t + cpair + 1];
                float4 v = make_float4((a2[t][0] + b0) * nz[t][0],
                                       (a2[t][1] + b1) * nz[t][1],
                                       (a2[t][2] + b0) * nz[t][2],
                                       (a2[t][3] + b1) * nz[t][3]);
                *(float4*)(gxp + t * 512) = v;
            }
            asm volatile("bar.sync %0, %1;" :: "r"(barid), "n"(64) : "memory");
            asm volatile("bar.sync %0, %1;" :: "r"(barid), "n"(64) : "memory");
            #pragma unroll
            for (int kk = 0; kk < 4; kk++) {
                uint4 vh = *(uint4*)(xfp + kk * 512);
                xh[kk][0] = vh.x; xh[kk][1] = vh.y; xh[kk][2] = vh.z; xh[kk][3] = vh.w;
            }
        } else {
            // f-warp: wait for g*dw, Euler-Maruyama update, publish new x frags
            asm volatile("bar.sync %0, %1;" :: "r"(barid), "n"(64) : "memory");
            float* ob = out + (size_t)(step + 1) * BATCH * DIM;
            #pragma unroll
            for (int t = 0; t < 8; t++) {
                float4 gv = *(const float4*)(gxp + t * 512);
                float bd0 = sb2d[8*t + cpair], bd1v = sb2d[8*t + cpair + 1];
                x[t][0] = fmaf(a2[t][0] + bd0,  DTC, x[t][0]) + gv.x;
                x[t][1] = fmaf(a2[t][1] + bd1v, DTC, x[t][1]) + gv.y;
                x[t][2] = fmaf(a2[t][2] + bd0,  DTC, x[t][2]) + gv.z;
                x[t][3] = fmaf(a2[t][3] + bd1v, DTC, x[t][3]) + gv.w;
                *(float2*)(ob + (size_t)row0 * DIM + 8*t + cpair)       = make_float2(x[t][0], x[t][1]);
                *(float2*)(ob + (size_t)(row0 + 8) * DIM + 8*t + cpair) = make_float2(x[t][2], x[t][3]);
            }
            pack_frags(x, xh);
            #pragma unroll
            for (int kk = 0; kk < 4; kk++)
                *(uint4*)(xfp + kk * 512) = make_uint4(xh[kk][0], xh[kk][1], xh[kk][2], xh[kk][3]);
            asm volatile("bar.sync %0, %1;" :: "r"(barid), "n"(64) : "memory");
        }
    }
}

extern "C" void kernel_launch(void* const* d_in, const int* in_sizes, int n_in,
                              void* d_out, int out_size)
{
    const float* x0    = (const float*)d_in[0];
    const float* noise = (const float*)d_in[2];
    const float* Wd1   = (const float*)d_in[3];
    const float* bd1   = (const float*)d_in[4];
    const float* Wd2   = (const float*)d_in[5];
    const float* bd2   = (const float*)d_in[6];
    const float* Wg1   = (const float*)d_in[7];
    const float* bg1   = (const float*)d_in[8];
    const float* Wg2   = (const float*)d_in[9];
    const float* bg2   = (const float*)d_in[10];
    float* out = (float*)d_out;

    cudaFuncSetAttribute(sde_wreg_kernel,
                         cudaFuncAttributeMaxDynamicSharedMemorySize, SMEM_TOTAL);
    sde_wreg_kernel<<<NBLK, THREADS, SMEM_TOTAL>>>(
        x0, noise, Wd1, bd1, Wd2, bd2, Wg1, bg1, Wg2, bg2, out);
}